// round 11
// baseline (speedup 1.0000x reference)
#include <cuda_runtime.h>
#include <cstdint>
#include <math.h>

#define NN 128
#define MM 64
#define BMAX 4096

// Scratch: beta-scaled cosine scores (2 MB). Static device array (no alloc).
__device__ float g_z[BMAX * NN];

__device__ __forceinline__ float softplus_f(float x) {
    return x > 0.f ? x + log1pf(expf(-x)) : log1pf(expf(x));
}

__device__ __forceinline__ float warp_sum(float v) {
    #pragma unroll
    for (int o = 16; o > 0; o >>= 1) v += __shfl_xor_sync(0xffffffffu, v, o);
    return v;
}

// ============================================================
// Kernel 1: pure stream. One warp per half-batch (64 rows).
// No smem, no block barriers, nothing but LDG/FMA/SHFL/STG.
// ============================================================
__global__ __launch_bounds__(256) void sim_kernel(
    const float* __restrict__ memory,   // [B, N, M]
    const float* __restrict__ key,      // [B, M]
    const float* __restrict__ beta_in)  // [B, 1]
{
    const int tid  = threadIdx.x;
    const int lane = tid & 31;
    const int task = blockIdx.x * 8 + (tid >> 5);   // warp-task id
    const int bb   = task >> 1;                     // batch
    const int h    = task & 1;                      // half (rows h*64..h*64+63)
    const int ll   = lane & 7;                      // lane within row group
    const int g    = lane >> 3;                     // row group 0..3

    // Key chunks ll and ll+8 (L2-resident after first half)
    const float4* key4 = reinterpret_cast<const float4*>(key + (size_t)bb * MM);
    const float4 k0 = __ldg(key4 + ll);
    const float4 k1 = __ldg(key4 + ll + 8);

    float kn = k0.x * k0.x + k0.y * k0.y + k0.z * k0.z + k0.w * k0.w
             + k1.x * k1.x + k1.y * k1.y + k1.z * k1.z + k1.w * k1.w;
    #pragma unroll
    for (int o = 4; o > 0; o >>= 1) kn += __shfl_xor_sync(0xffffffffu, kn, o);

    const float beta = softplus_f(__ldg(beta_in + bb));
    const float bk   = beta / fmaxf(sqrtf(kn), 1e-8f);   // beta / key_norm

    const float4* base = reinterpret_cast<const float4*>(memory)
                       + (size_t)bb * (NN * MM / 4) + (h * 64) * 16;
    float* zout = g_z + (size_t)bb * NN + h * 64;

    // 16 passes of 4 rows, in 4 blocks: batch 8 LDG.128, then 4 independent
    // fused-reduce chains. No other work in the stream.
    #pragma unroll
    for (int blk = 0; blk < 4; ++blk) {
        float4 va[8];
        #pragma unroll
        for (int u = 0; u < 4; ++u) {
            const int row = (blk * 4 + u) * 4 + g;
            va[2 * u]     = __ldcs(base + row * 16 + ll);
            va[2 * u + 1] = __ldcs(base + row * 16 + ll + 8);
        }
        #pragma unroll
        for (int u = 0; u < 4; ++u) {
            const int row = (blk * 4 + u) * 4 + g;
            float4 v0 = va[2 * u], v1 = va[2 * u + 1];
            float dp = v0.x * k0.x + v0.y * k0.y + v0.z * k0.z + v0.w * k0.w
                     + v1.x * k1.x + v1.y * k1.y + v1.z * k1.z + v1.w * k1.w;
            float np = v0.x * v0.x + v0.y * v0.y + v0.z * v0.z + v0.w * v0.w
                     + v1.x * v1.x + v1.y * v1.y + v1.z * v1.z + v1.w * v1.w;

            // Fused 8-lane reduce: lanes ll<4 end with dp total, ll>=4 np.
            float send = (lane & 4) ? dp : np;
            float recv = __shfl_xor_sync(0xffffffffu, send, 4);
            float v = ((lane & 4) ? np : dp) + recv;
            v += __shfl_xor_sync(0xffffffffu, v, 2);
            v += __shfl_xor_sync(0xffffffffu, v, 1);
            float other = __shfl_xor_sync(0xffffffffu, v, 4); // ll==0: np

            if (ll == 0) {
                float mn = fmaxf(sqrtf(other), 1e-8f);
                zout[row] = (v / mn) * bk;          // 4 consecutive floats/warp
            }
        }
    }
}

// ============================================================
// Kernel 2: tiny epilogue, one block per batch.
// ============================================================
__global__ __launch_bounds__(128) void ep_kernel(
    const float* __restrict__ g_in,     // [B, 1]
    const float* __restrict__ s_in,     // [B, 3]
    const float* __restrict__ gamma_in, // [B, 1]
    const float* __restrict__ w_prev,   // [B, N]
    float* __restrict__ out)            // [B, N]
{
    __shared__ float shw[NN];
    __shared__ float redA[4], redB[4];

    const int b    = blockIdx.x;
    const int tid  = threadIdx.x;
    const int lane = tid & 31;
    const int wid  = tid >> 5;

    const float z   = g_z[(size_t)b * NN + tid];
    const float wpv = w_prev[(size_t)b * NN + tid];

    const float gg = 1.f / (1.f + __expf(-g_in[b]));
    float s0 = s_in[b * 3 + 0], s1 = s_in[b * 3 + 1], s2 = s_in[b * 3 + 2];
    const float smax = fmaxf(s0, fmaxf(s1, s2));
    const float e0 = __expf(s0 - smax), e1 = __expf(s1 - smax),
                e2 = __expf(s2 - smax);
    const float sinv = 1.f / (e0 + e1 + e2);
    const float t0 = e0 * sinv, t1 = e1 * sinv, t2 = e2 * sinv;
    const float gamma = 1.f + softplus_f(gamma_in[b]);

    // softmax without max-subtraction: |z| <= beta (cos in [-1,1]), safe
    const float e = __expf(z);
    float se = warp_sum(e);
    if (lane == 0) redB[wid] = se;
    __syncthreads();
    const float tot = redB[0] + redB[1] + redB[2] + redB[3];
    const float wc = e / tot;

    const float wg = gg * wc + (1.f - gg) * wpv;
    shw[tid] = wg;
    __syncthreads();

    const float wh = shw[(tid + NN - 1) & (NN - 1)] * t0
                   + wg * t1
                   + shw[(tid + 1) & (NN - 1)] * t2;

    const float w = __powf(wh, gamma);
    float sw2 = warp_sum(w);
    if (lane == 0) redA[wid] = sw2;
    __syncthreads();
    const float tw = redA[0] + redA[1] + redA[2] + redA[3] + 1e-16f;

    out[(size_t)b * NN + tid] = w / tw;
}

extern "C" void kernel_launch(void* const* d_in, const int* in_sizes, int n_in,
                              void* d_out, int out_size) {
    const float* memory  = (const float*)d_in[0];  // [B, N, M]
    const float* k       = (const float*)d_in[1];  // [B, M]
    const float* beta    = (const float*)d_in[2];  // [B, 1]
    const float* g       = (const float*)d_in[3];  // [B, 1]
    const float* s       = (const float*)d_in[4];  // [B, 3]
    const float* gamma   = (const float*)d_in[5];  // [B, 1]
    const float* w_prev  = (const float*)d_in[6];  // [B, N]
    float* out = (float*)d_out;

    const int B = in_sizes[0] / (NN * MM);
    // Kernel 1: 2 warp-tasks per batch, 8 warps per 256-thread CTA.
    sim_kernel<<<(B * 2) / 8, 256>>>(memory, k, beta);
    // Kernel 2: one 128-thread block per batch.
    ep_kernel<<<B, 128>>>(g, s, gamma, w_prev, out);
}